// round 15
// baseline (speedup 1.0000x reference)
#include <cuda_runtime.h>
#include <cstdint>

#define B_ 4
#define S_ 2048
#define E_ 1024
#define H_ 16
#define D_ 64
#define MTOT (B_*S_)   // 8192

// Scratch (device globals: allocation-free rule)
__device__ float g_Q[B_*S_*E_];
__device__ float g_K[B_*S_*E_];
__device__ float g_V[B_*S_*E_];
__device__ float g_Ctx[B_*S_*E_];

// ---------------------------------------------------------------------------
// helpers
// ---------------------------------------------------------------------------
// HMMA.TF32 reads the top 19 bits of an fp32 register. +0x1000 on the bit
// pattern = round-to-nearest (ties away) in 1 IADD. (== cvt.rna numerics.)
__device__ __forceinline__ uint32_t rtf(float x) {
    return __float_as_uint(x) + 0x1000u;
}

__device__ __forceinline__ void mma_tf32(float* c, const uint32_t* a,
                                         uint32_t b0, uint32_t b1) {
    asm volatile(
        "mma.sync.aligned.m16n8k8.row.col.f32.tf32.tf32.f32 "
        "{%0,%1,%2,%3}, {%4,%5,%6,%7}, {%8,%9}, {%0,%1,%2,%3};"
        : "+f"(c[0]), "+f"(c[1]), "+f"(c[2]), "+f"(c[3])
        : "r"(a[0]), "r"(a[1]), "r"(a[2]), "r"(a[3]), "r"(b0), "r"(b1));
}

__device__ __forceinline__ void cp_async16(uint32_t saddr, const void* g) {
    asm volatile("cp.async.cg.shared.global [%0], [%1], 16;"
                 :: "r"(saddr), "l"(g));
}
__device__ __forceinline__ void cp_commit() {
    asm volatile("cp.async.commit_group;");
}
template <int N>
__device__ __forceinline__ void cp_wait() {
    asm volatile("cp.async.wait_group %0;" :: "n"(N));
}

// ---------------------------------------------------------------------------
// tf32 GEMM (NT): ROUND-6 VERBATIM (147us/GEMM proven). CTA 128x128, BK=16,
// 256 thr (8 warps, 2x4), warp tile 64x32. 3-stage cp.async, one sync/k-tile.
// ---------------------------------------------------------------------------
#define GP 20
#define GSTG (128 * GP)
#define GEMM_SMEM_FLOATS (6 * GSTG)   // As[3] + Bs[3] = 61440 B

__global__ __launch_bounds__(256) void gemm_tf32_nt(
    const float* __restrict__ A, const float* __restrict__ Bm,
    const float* __restrict__ bias, float* __restrict__ C,
    int M, int N, int K)
{
    extern __shared__ float smg[];
    float* As = smg;             // 3 buffers of GSTG
    float* Bs = smg + 3 * GSTG;

    const int tid = threadIdx.x;
    const int warp = tid >> 5, lane = tid & 31;
    const int g = lane >> 2, q = lane & 3;
    const int wm = warp >> 2;          // 0..1
    const int wn = warp & 3;           // 0..3
    const int bm = blockIdx.y, bn = blockIdx.x;

    const int lrow = tid >> 1;
    const int lcol = (tid & 1) * 8;
    const float* Ap = A + (size_t)(bm * 128 + lrow) * K + lcol;
    const float* Bp = Bm + (size_t)(bn * 128 + lrow) * K + lcol;

    uint32_t sA0 = (uint32_t)__cvta_generic_to_shared(&As[lrow * GP + lcol]);
    uint32_t sB0 = (uint32_t)__cvta_generic_to_shared(&Bs[lrow * GP + lcol]);
    const uint32_t stg = (uint32_t)(GSTG * sizeof(float));

    float acc[4][4][4];
#pragma unroll
    for (int i = 0; i < 4; i++)
#pragma unroll
        for (int j = 0; j < 4; j++)
#pragma unroll
            for (int t = 0; t < 4; t++) acc[i][j][t] = 0.f;

    const int nt = K / 16;
#pragma unroll
    for (int p = 0; p < 2; p++) {
        const float* ap = Ap + p * 16;
        const float* bp = Bp + p * 16;
        cp_async16(sA0 + p * stg, ap);
        cp_async16(sA0 + p * stg + 16, ap + 4);
        cp_async16(sB0 + p * stg, bp);
        cp_async16(sB0 + p * stg + 16, bp + 4);
        cp_commit();
    }

    for (int kt = 0; kt < nt; kt++) {
        const int cur = kt % 3;
        cp_wait<1>();
        __syncthreads();
        if (kt + 2 < nt) {
            const int nxt = (kt + 2) % 3;
            const float* ap = Ap + (kt + 2) * 16;
            const float* bp = Bp + (kt + 2) * 16;
            cp_async16(sA0 + nxt * stg, ap);
            cp_async16(sA0 + nxt * stg + 16, ap + 4);
            cp_async16(sB0 + nxt * stg, bp);
            cp_async16(sB0 + nxt * stg + 16, bp + 4);
            cp_commit();
        } else {
            cp_commit();
        }

        const float* as = As + cur * GSTG;
        const float* bs = Bs + cur * GSTG;
#pragma unroll
        for (int kh = 0; kh < 2; kh++) {
            const int k0 = kh * 8;
            uint32_t af[4][4];
#pragma unroll
            for (int i = 0; i < 4; i++) {
                int r = wm * 64 + i * 16 + g;
                af[i][0] = rtf(as[r * GP + k0 + q]);
                af[i][1] = rtf(as[(r + 8) * GP + k0 + q]);
                af[i][2] = rtf(as[r * GP + k0 + q + 4]);
                af[i][3] = rtf(as[(r + 8) * GP + k0 + q + 4]);
            }
#pragma unroll
            for (int j = 0; j < 4; j++) {
                int n = wn * 32 + j * 8 + g;
                uint32_t bf0 = rtf(bs[n * GP + k0 + q]);
                uint32_t bf1 = rtf(bs[n * GP + k0 + q + 4]);
#pragma unroll
                for (int i = 0; i < 4; i++)
                    mma_tf32(acc[i][j], af[i], bf0, bf1);
            }
        }
    }

#pragma unroll
    for (int i = 0; i < 4; i++) {
        int r0 = bm * 128 + wm * 64 + i * 16 + g;
#pragma unroll
        for (int j = 0; j < 4; j++) {
            int col = bn * 128 + wn * 32 + j * 8 + 2 * q;
            float bx = 0.f, by = 0.f;
            if (bias) { bx = bias[col]; by = bias[col + 1]; }
            float2 v0 = make_float2(acc[i][j][0] + bx, acc[i][j][1] + by);
            float2 v1 = make_float2(acc[i][j][2] + bx, acc[i][j][3] + by);
            *(float2*)&C[(size_t)r0 * N + col] = v0;
            *(float2*)&C[(size_t)(r0 + 8) * N + col] = v1;
        }
    }
}

// ---------------------------------------------------------------------------
// tf32 flash attention — round-14 (cp.async K/V pipeline) + REGISTER P:
// the PV A-fragments are built from the post-softmax score registers via a
// quad shuffle exchange (C-layout -> A-layout is a within-quad permutation:
// col j*8+q lives at lane (g<<2)|(q>>1), component q&1; col +4 at that
// lane +2). Removes the 34.8KB Ps buffer (smem 105->70.7KB -> 3 CTAs/SM)
// and 32 STS + 64 LDS per iter. rtf applied post-shuffle (identical bits).
// launch_bounds(128,3) caps regs at 170 to let 3 CTAs fit.
// ---------------------------------------------------------------------------
#define QP 68
#define VP 72
#define FLASH_SMEM_FLOATS (128*QP + 64*QP + 64*VP)   // Q,K,V = 17664 (70656 B)

__global__ __launch_bounds__(128, 3) void flash_tf32_kernel(
    const float* __restrict__ Q, const float* __restrict__ K,
    const float* __restrict__ V, float* __restrict__ O)
{
    extern __shared__ float sm[];
    float* Qs = sm;                    // [128][QP]
    float* Ks = Qs + 128 * QP;         // [64][QP]
    float* Vs = Ks + 64 * QP;          // [64][VP]

    const int tid = threadIdx.x;
    const int warp = tid >> 5, lane = tid & 31;
    const int g = lane >> 2, q = lane & 3;
    const int b = blockIdx.z, h = blockIdx.y;
    const int q0 = blockIdx.x * 128;
    const int base = b * S_ * E_ + h * D_;
    const int r0 = warp * 32 + g;
    const int r1 = r0 + 16;
    const int src0 = (g << 2) | (q >> 1);   // quad source for cols q
    const int src1 = src0 | 2;              // quad source for cols q+4
    const bool sel = (q & 1);

    // Stage Q tile [128 q][64 d], scaled by 1/8 (exact) + RN bias.
#pragma unroll
    for (int t = 0; t < 16; t++) {
        int u = tid + t * 128;
        int rr = u >> 4, cc = (u & 15) * 4;
        float4 v = *(const float4*)&Q[base + (size_t)(q0 + rr) * E_ + cc];
        uint4 o;
        o.x = rtf(v.x * 0.125f); o.y = rtf(v.y * 0.125f);
        o.z = rtf(v.z * 0.125f); o.w = rtf(v.w * 0.125f);
        *(uint4*)&Qs[rr * QP + cc] = o;
    }

    const uint32_t sKs = (uint32_t)__cvta_generic_to_shared(Ks);
    const uint32_t sVs = (uint32_t)__cvta_generic_to_shared(Vs);

    // prologue: async-stage K(0) then V(0) as separate groups
#pragma unroll
    for (int t = 0; t < 8; t++) {
        int u = tid + t * 128;
        int rr = u >> 4, cc = (u & 15) * 4;
        cp_async16(sKs + (uint32_t)(rr * QP + cc) * 4u,
                   &K[base + (size_t)rr * E_ + cc]);
    }
    cp_commit();
#pragma unroll
    for (int t = 0; t < 8; t++) {
        int u = tid + t * 128;
        int rr = u >> 4, cc = (u & 15) * 4;
        cp_async16(sVs + (uint32_t)(rr * VP + cc) * 4u,
                   &V[base + (size_t)rr * E_ + cc]);
    }
    cp_commit();

    float m0a = -1e30f, m0b = -1e30f, m1a = -1e30f, m1b = -1e30f;
    float l0a = 0.f, l0b = 0.f, l1a = 0.f, l1b = 0.f;
    float oacc0[8][4], oacc1[8][4];
#pragma unroll
    for (int j = 0; j < 8; j++)
#pragma unroll
        for (int t = 0; t < 4; t++) { oacc0[j][t] = 0.f; oacc1[j][t] = 0.f; }

    for (int t0 = 0; t0 < S_; t0 += 64) {
        // K(t) resident (V(t) may still be in flight); also orders Qs staging
        cp_wait<1>();
        __syncthreads();

        // ---- S = Q @ K^T (m32 x n64, k=64); RN bias on K frags ----
        float s0[8][4], s1[8][4];
#pragma unroll
        for (int j = 0; j < 8; j++)
#pragma unroll
            for (int t = 0; t < 4; t++) { s0[j][t] = 0.f; s1[j][t] = 0.f; }

#pragma unroll
        for (int ks = 0; ks < 8; ks++) {
            int k0 = ks * 8;
            uint32_t a0[4], a1[4];
            a0[0] = __float_as_uint(Qs[r0 * QP + k0 + q]);
            a0[1] = __float_as_uint(Qs[(r0 + 8) * QP + k0 + q]);
            a0[2] = __float_as_uint(Qs[r0 * QP + k0 + q + 4]);
            a0[3] = __float_as_uint(Qs[(r0 + 8) * QP + k0 + q + 4]);
            a1[0] = __float_as_uint(Qs[r1 * QP + k0 + q]);
            a1[1] = __float_as_uint(Qs[(r1 + 8) * QP + k0 + q]);
            a1[2] = __float_as_uint(Qs[r1 * QP + k0 + q + 4]);
            a1[3] = __float_as_uint(Qs[(r1 + 8) * QP + k0 + q + 4]);
#pragma unroll
            for (int j = 0; j < 8; j++) {
                int n = j * 8 + g;
                uint32_t b0 = rtf(Ks[n * QP + k0 + q]);
                uint32_t b1 = rtf(Ks[n * QP + k0 + q + 4]);
                mma_tf32(s0[j], a0, b0, b1);
                mma_tf32(s1[j], a1, b0, b1);
            }
        }

        __syncthreads();   // all warps done reading Ks
        if (t0 + 64 < S_) {     // async-stage K(t+1); overlaps softmax+PV
#pragma unroll
            for (int t = 0; t < 8; t++) {
                int u = tid + t * 128;
                int rr = u >> 4, cc = (u & 15) * 4;
                cp_async16(sKs + (uint32_t)(rr * QP + cc) * 4u,
                           &K[base + (size_t)(t0 + 64 + rr) * E_ + cc]);
            }
        }
        cp_commit();       // (empty at tail keeps group counts aligned)

        // ---- online softmax, m-tile 0: p written back into s0 regs ----
        {
            float mxa = -1e30f, mxb = -1e30f;
#pragma unroll
            for (int j = 0; j < 8; j++) {
                mxa = fmaxf(mxa, fmaxf(s0[j][0], s0[j][1]));
                mxb = fmaxf(mxb, fmaxf(s0[j][2], s0[j][3]));
            }
            mxa = fmaxf(mxa, __shfl_xor_sync(0xffffffffu, mxa, 1));
            mxa = fmaxf(mxa, __shfl_xor_sync(0xffffffffu, mxa, 2));
            mxb = fmaxf(mxb, __shfl_xor_sync(0xffffffffu, mxb, 1));
            mxb = fmaxf(mxb, __shfl_xor_sync(0xffffffffu, mxb, 2));
            float nma = fmaxf(m0a, mxa), nmb = fmaxf(m0b, mxb);
            float ala = __expf(m0a - nma), alb = __expf(m0b - nmb);
            m0a = nma; m0b = nmb;
            float rsa = 0.f, rsb = 0.f;
#pragma unroll
            for (int j = 0; j < 8; j++) {
                s0[j][0] = __expf(s0[j][0] - nma);
                s0[j][1] = __expf(s0[j][1] - nma);
                s0[j][2] = __expf(s0[j][2] - nmb);
                s0[j][3] = __expf(s0[j][3] - nmb);
                rsa += s0[j][0] + s0[j][1];
                rsb += s0[j][2] + s0[j][3];
            }
            rsa += __shfl_xor_sync(0xffffffffu, rsa, 1);
            rsa += __shfl_xor_sync(0xffffffffu, rsa, 2);
            rsb += __shfl_xor_sync(0xffffffffu, rsb, 1);
            rsb += __shfl_xor_sync(0xffffffffu, rsb, 2);
            l0a = l0a * ala + rsa;
            l0b = l0b * alb + rsb;
#pragma unroll
            for (int j = 0; j < 8; j++) {
                oacc0[j][0] *= ala; oacc0[j][1] *= ala;
                oacc0[j][2] *= alb; oacc0[j][3] *= alb;
            }
        }
        // ---- online softmax, m-tile 1 ----
        {
            float mxa = -1e30f, mxb = -1e30f;
#pragma unroll
            for (int j = 0; j < 8; j++) {
                mxa = fmaxf(mxa, fmaxf(s1[j][0], s1[j][1]));
                mxb = fmaxf(mxb, fmaxf(s1[j][2], s1[j][3]));
            }
            mxa = fmaxf(mxa, __shfl_xor_sync(0xffffffffu, mxa, 1));
            mxa = fmaxf(mxa, __shfl_xor_sync(0xffffffffu, mxa, 2));
            mxb = fmaxf(mxb, __shfl_xor_sync(0xffffffffu, mxb, 1));
            mxb = fmaxf(mxb, __shfl_xor_sync(0xffffffffu, mxb, 2));
            float nma = fmaxf(m1a, mxa), nmb = fmaxf(m1b, mxb);
            float ala = __expf(m1a - nma), alb = __expf(m1b - nmb);
            m1a = nma; m1b = nmb;
            float rsa = 0.f, rsb = 0.f;
#pragma unroll
            for (int j = 0; j < 8; j++) {
                s1[j][0] = __expf(s1[j][0] - nma);
                s1[j][1] = __expf(s1[j][1] - nma);
                s1[j][2] = __expf(s1[j][2] - nmb);
                s1[j][3] = __expf(s1[j][3] - nmb);
                rsa += s1[j][0] + s1[j][1];
                rsb += s1[j][2] + s1[j][3];
            }
            rsa += __shfl_xor_sync(0xffffffffu, rsa, 1);
            rsa += __shfl_xor_sync(0xffffffffu, rsa, 2);
            rsb += __shfl_xor_sync(0xffffffffu, rsb, 1);
            rsb += __shfl_xor_sync(0xffffffffu, rsb, 2);
            l1a = l1a * ala + rsa;
            l1b = l1b * alb + rsb;
#pragma unroll
            for (int j = 0; j < 8; j++) {
                oacc1[j][0] *= ala; oacc1[j][1] *= ala;
                oacc1[j][2] *= alb; oacc1[j][3] *= alb;
            }
        }

        // V(t) resident (K(t+1) may still be in flight)
        cp_wait<1>();
        __syncthreads();

        // ---- O += P @ V; P A-frags via quad shuffle from s0/s1 regs ----
#pragma unroll
        for (int ks = 0; ks < 8; ks++) {
            int k0 = ks * 8;
            uint32_t a0[4], a1[4];
            {
                float x0 = __shfl_sync(0xffffffffu, s0[ks][0], src0);
                float x1 = __shfl_sync(0xffffffffu, s0[ks][1], src0);
                float x2 = __shfl_sync(0xffffffffu, s0[ks][2], src0);
                float x3 = __shfl_sync(0xffffffffu, s0[ks][3], src0);
                float y0 = __shfl_sync(0xffffffffu, s0[ks][0], src1);
                float y1 = __shfl_sync(0xffffffffu, s0[ks][1], src1);
                float y2 = __shfl_sync(0xffffffffu, s0[ks][2], src1);
                float y3 = __shfl_sync(0xffffffffu, s0[ks][3], src1);
                a0[0] = rtf(sel ? x1 : x0);
                a0[1] = rtf(sel ? x3 : x2);
                a0[2] = rtf(sel ? y1 : y0);
                a0[3] = rtf(sel ? y3 : y2);
            }
            {
                float x0 = __shfl_sync(0xffffffffu, s1[ks][0], src0);
                float x1 = __shfl_sync(0xffffffffu, s1[ks][1], src0);
                float x2 = __shfl_sync(0xffffffffu, s1[ks][2], src0);
                float x3 = __shfl_sync(0xffffffffu, s1[ks][3], src0);
                float y0 = __shfl_sync(0xffffffffu, s1[ks][0], src1);
                float y1 = __shfl_sync(0xffffffffu, s1[ks][1], src1);
                float y2 = __shfl_sync(0xffffffffu, s1[ks][2], src1);
                float y3 = __shfl_sync(0xffffffffu, s1[ks][3], src1);
                a1[0] = rtf(sel ? x1 : x0);
                a1[1] = rtf(sel ? x3 : x2);
                a1[2] = rtf(sel ? y1 : y0);
                a1[3] = rtf(sel ? y3 : y2);
            }
#pragma unroll
            for (int j = 0; j < 8; j++) {
                uint32_t b0 = rtf(Vs[(k0 + q) * VP + j * 8 + g]);
                uint32_t b1 = rtf(Vs[(k0 + q + 4) * VP + j * 8 + g]);
                mma_tf32(oacc0[j], a0, b0, b1);
                mma_tf32(oacc1[j], a1, b0, b1);
            }
        }

        __syncthreads();   // all warps done reading Vs
        if (t0 + 64 < S_) {     // async-stage V(t+1); overlaps next QK^T
#pragma unroll
            for (int t = 0; t < 8; t++) {
                int u = tid + t * 128;
                int rr = u >> 4, cc = (u & 15) * 4;
                cp_async16(sVs + (uint32_t)(rr * VP + cc) * 4u,
                           &V[base + (size_t)(t0 + 64 + rr) * E_ + cc]);
            }
        }
        cp_commit();
    }

    // normalize + write ctx in [B,S,H,D] layout
    float i0a = 1.f / l0a, i0b = 1.f / l0b, i1a = 1.f / l1a, i1b = 1.f / l1b;
#pragma unroll
    for (int j = 0; j < 8; j++) {
        int col = j * 8 + 2 * q;
        *(float2*)&O[base + (size_t)(q0 + r0) * E_ + col] =
            make_float2(oacc0[j][0] * i0a, oacc0[j][1] * i0a);
        *(float2*)&O[base + (size_t)(q0 + r0 + 8) * E_ + col] =
            make_float2(oacc0[j][2] * i0b, oacc0[j][3] * i0b);
        *(float2*)&O[base + (size_t)(q0 + r1) * E_ + col] =
            make_float2(oacc1[j][0] * i1a, oacc1[j][1] * i1a);
        *(float2*)&O[base + (size_t)(q0 + r1 + 8) * E_ + col] =
            make_float2(oacc1[j][2] * i1b, oacc1[j][3] * i1b);
    }
}

// ---------------------------------------------------------------------------
extern "C" void kernel_launch(void* const* d_in, const int* in_sizes, int n_in,
                              void* d_out, int out_size)
{
    const float* X  = (const float*)d_in[0];
    const float* Wq = (const float*)d_in[1];
    const float* Wk = (const float*)d_in[2];
    const float* Wv = (const float*)d_in[3];
    const float* Wo = (const float*)d_in[4];
    const float* bo = (const float*)d_in[5];
    float* out = (float*)d_out;

    float *Qp, *Kp, *Vp, *Cp;
    cudaGetSymbolAddress((void**)&Qp, g_Q);
    cudaGetSymbolAddress((void**)&Kp, g_K);
    cudaGetSymbolAddress((void**)&Vp, g_V);
    cudaGetSymbolAddress((void**)&Cp, g_Ctx);

    int gemm_smem = GEMM_SMEM_FLOATS * (int)sizeof(float);   // 61440
    cudaFuncSetAttribute(gemm_tf32_nt,
                         cudaFuncAttributeMaxDynamicSharedMemorySize, gemm_smem);
    int flash_smem = FLASH_SMEM_FLOATS * (int)sizeof(float); // 70656
    cudaFuncSetAttribute(flash_tf32_kernel,
                         cudaFuncAttributeMaxDynamicSharedMemorySize, flash_smem);

    dim3 gemm_grid(E_ / 128, MTOT / 128);   // (8, 64)
    gemm_tf32_nt<<<gemm_grid, 256, gemm_smem>>>(X, Wq, nullptr, Qp, MTOT, E_, E_);
    gemm_tf32_nt<<<gemm_grid, 256, gemm_smem>>>(X, Wk, nullptr, Kp, MTOT, E_, E_);
    gemm_tf32_nt<<<gemm_grid, 256, gemm_smem>>>(X, Wv, nullptr, Vp, MTOT, E_, E_);

    flash_tf32_kernel<<<dim3(S_ / 128, H_, B_), 128, flash_smem>>>(Qp, Kp, Vp, Cp);

    gemm_tf32_nt<<<gemm_grid, 256, gemm_smem>>>(Cp, Wo, bo, out, MTOT, E_, E_);
}